// round 15
// baseline (speedup 1.0000x reference)
#include <cuda_runtime.h>
#include <cuda_bf16.h>
#include <math.h>
#include <stdint.h>

#define Bsz  16
#define Ntok 2048
#define Cdim 768
#define BN   (Bsz*Ntok)

// ---------------- scratch (static device globals; no allocation) ------------
__device__ float g_y [(size_t)BN*Cdim];                 // conv+residual output
__device__ float g_x2[(size_t)BN*Cdim];                 // layernormed x
__device__ __align__(16) __nv_bfloat16 g_xh[(size_t)BN*Cdim];   // hi split
__device__ __align__(16) __nv_bfloat16 g_xl[(size_t)BN*Cdim];   // lo split
__device__ __align__(16) __nv_bfloat16 g_wh[3*Cdim*Cdim];       // W hi [tap][co][ci]
__device__ __align__(16) __nv_bfloat16 g_wl[3*Cdim*Cdim];       // W lo
__device__ float g_dist[(size_t)Bsz*Ntok*Ntok];         // 268 MB distance matrix
__device__ float g_tw [BN];
__device__ float g_sq [BN];
__device__ float g_den[BN];
__device__ float g_sc [BN];
__device__ float g_dmax[Bsz];
__device__ int   g_idn[Bsz*2];
__device__ float g_aw [Bsz*2];
__device__ int   g_cl [BN];
__device__ float g_nw [BN];

// ---------------- mma/ldmatrix/cp.async helpers ------------------------------
__device__ __forceinline__ uint32_t smem_u32(const void* p) {
    uint32_t a;
    asm("{ .reg .u64 t; cvta.to.shared.u64 t, %1; cvt.u32.u64 %0, t; }"
        : "=r"(a) : "l"(p));
    return a;
}

__device__ __forceinline__ void cpa16(uint32_t d, const void* s, int sz) {
    asm volatile("cp.async.cg.shared.global [%0], [%1], 16, %2;"
                 :: "r"(d), "l"(s), "r"(sz));
}

__device__ __forceinline__ void ldm4(uint32_t* r, uint32_t a) {
    asm volatile("ldmatrix.sync.aligned.m8n8.x4.shared.b16 {%0,%1,%2,%3}, [%4];"
                 : "=r"(r[0]), "=r"(r[1]), "=r"(r[2]), "=r"(r[3]) : "r"(a));
}

__device__ __forceinline__ void mma16816(float* c, const uint32_t* a, const uint32_t* b) {
    asm volatile(
        "mma.sync.aligned.m16n8k16.row.col.f32.bf16.bf16.f32 "
        "{%0,%1,%2,%3}, {%4,%5,%6,%7}, {%8,%9}, {%0,%1,%2,%3};"
        : "+f"(c[0]), "+f"(c[1]), "+f"(c[2]), "+f"(c[3])
        : "r"(a[0]), "r"(a[1]), "r"(a[2]), "r"(a[3]), "r"(b[0]), "r"(b[1]));
}

// ---- gram smem geometry: 4 matrices of 128 rows x 32 bf16, pitch 80B, 2 stg
#define PITCH 80
#define MATB  (128*PITCH)     // 10240
#define A_HI  0
#define A_LO  (1*MATB)
#define B_HI  (2*MATB)
#define B_LO  (3*MATB)
#define STG   (4*MATB)        // 40960
#define SMEM_DYN (2*STG)      // 81920

// ---- conv smem geometry: A 128 rows, B 256 rows, pitch 80B, 2 stages --------
#define A2_HI 0
#define A2_LO (128*PITCH)             // 10240
#define B2_HI (2*128*PITCH)           // 20480
#define B2_LO (2*128*PITCH + 256*PITCH)  // 40960
#define STG2  (2*128*PITCH + 2*256*PITCH) // 61440
#define SMEM_CONV (2*STG2)            // 122880

// ---------------- misc small kernels ----------------------------------------
__global__ void k_init() {
    int t = threadIdx.x;
    if (t < Bsz) g_dmax[t] = 0.0f;
}

__global__ void k_splitw(const float* __restrict__ w) {
    int i = blockIdx.x * 256 + threadIdx.x;
    if (i >= 3 * Cdim * Cdim) return;
    int ci = i % Cdim;
    int co = (i / Cdim) % Cdim;
    int k  = i / (Cdim * Cdim);
    float v = w[((size_t)co * Cdim + ci) * 3 + k];
    __nv_bfloat16 h = __float2bfloat16(v);
    g_wh[i] = h;
    g_wl[i] = __float2bfloat16(v - __bfloat162float(h));
}

__device__ __forceinline__ void split4(const float* src, size_t i) {
    float4 v = *(const float4*)(src + i);
    __nv_bfloat16 h0 = __float2bfloat16(v.x), h1 = __float2bfloat16(v.y);
    __nv_bfloat16 h2 = __float2bfloat16(v.z), h3 = __float2bfloat16(v.w);
    __nv_bfloat162* ph = (__nv_bfloat162*)(g_xh + i);
    __nv_bfloat162* pl = (__nv_bfloat162*)(g_xl + i);
    ph[0] = __nv_bfloat162(h0, h1);
    ph[1] = __nv_bfloat162(h2, h3);
    pl[0] = __nv_bfloat162(__float2bfloat16(v.x - __bfloat162float(h0)),
                           __float2bfloat16(v.y - __bfloat162float(h1)));
    pl[1] = __nv_bfloat162(__float2bfloat16(v.z - __bfloat162float(h2)),
                           __float2bfloat16(v.w - __bfloat162float(h3)));
}

__global__ void __launch_bounds__(256) k_split_in(const float* __restrict__ src) {
    split4(src, ((size_t)blockIdx.x * 256 + threadIdx.x) * 4);
}
__global__ void __launch_bounds__(256) k_split_x2() {
    split4(g_x2, ((size_t)blockIdx.x * 256 + threadIdx.x) * 4);
}

// ================== CONV: block 128x256, warp tile 64x64 =====================
__device__ __forceinline__ void conv_load2(uint32_t st, int t, int m0, int n0, int c) {
    int tap = c / 24, kc = (c % 24) * 32;
    // A: 128 rows, 2 segs/thread per matrix
    {
        int r = t >> 1, sg = (t & 1) * 2;
        int m = m0 + r;
        int loc = (m & (Ntok - 1)) + tap - 1;
        bool v = (loc >= 0 && loc < Ntok);
        long long ao = (long long)(m + tap - 1) * Cdim + kc;
        uint32_t ro = (uint32_t)r * PITCH;
        #pragma unroll
        for (int i = 0; i < 2; i++) {
            int seg = sg + i;
            uint32_t so = ro + seg * 16;
            cpa16(st + A2_HI + so, v ? (const void*)(g_xh + ao + seg * 8) : (const void*)g_xh, v ? 16 : 0);
            cpa16(st + A2_LO + so, v ? (const void*)(g_xl + ao + seg * 8) : (const void*)g_xl, v ? 16 : 0);
        }
    }
    // B: 256 rows (out channels), 1 row/thread, 4 segs per matrix
    {
        size_t wo = ((size_t)tap * Cdim + n0 + t) * Cdim + kc;
        uint32_t ro = (uint32_t)t * PITCH;
        #pragma unroll
        for (int i = 0; i < 4; i++) {
            cpa16(st + B2_HI + ro + i * 16, g_wh + wo + i * 8, 16);
            cpa16(st + B2_LO + ro + i * 16, g_wl + wo + i * 8, 16);
        }
    }
    asm volatile("cp.async.commit_group;");
}

__global__ void __launch_bounds__(256) k_conv_mma(const float* __restrict__ x) {
    extern __shared__ char sm[];
    uint32_t sb = smem_u32(sm);
    int t = threadIdx.x, l = t & 31, w = t >> 5;
    int wm = w & 1, wn = w >> 1;           // 2 x 4 warp grid, 64x64 per warp
    int m0 = blockIdx.y * 128, n0 = blockIdx.x * 256;

    float acc[4][8][4];
    #pragma unroll
    for (int i = 0; i < 4; i++)
        #pragma unroll
        for (int j = 0; j < 8; j++)
            #pragma unroll
            for (int q = 0; q < 4; q++) acc[i][j][q] = 0.f;

    const int C = 72;
    conv_load2(sb, t, m0, n0, 0);
    for (int c = 0; c < C; c++) {
        asm volatile("cp.async.wait_group 0;");
        __syncthreads();
        if (c + 1 < C)
            conv_load2(sb + ((c + 1) & 1) * STG2, t, m0, n0, c + 1);
        uint32_t st = sb + (c & 1) * STG2;
        #pragma unroll
        for (int kh = 0; kh < 2; kh++) {
            uint32_t ah[4][4], al[4][4], bh[8][2], bl[8][2];
            uint32_t aoff = ((l >> 4) * 8 + kh * 16) * 2;
            int arow = wm * 64 + (l & 15);
            #pragma unroll
            for (int mt = 0; mt < 4; mt++) {
                ldm4(ah[mt], st + A2_HI + (uint32_t)(arow + mt * 16) * PITCH + aoff);
                ldm4(al[mt], st + A2_LO + (uint32_t)(arow + mt * 16) * PITCH + aoff);
            }
            int brow = wn * 64 + (l & 7) + ((l >> 4) & 1) * 8;
            uint32_t boff = (((l >> 3) & 1) * 8 + kh * 16) * 2;
            #pragma unroll
            for (int p = 0; p < 4; p++) {
                uint32_t tmp[4];
                ldm4(tmp, st + B2_HI + (uint32_t)(brow + p * 16) * PITCH + boff);
                bh[2 * p][0] = tmp[0]; bh[2 * p][1] = tmp[1];
                bh[2 * p + 1][0] = tmp[2]; bh[2 * p + 1][1] = tmp[3];
                ldm4(tmp, st + B2_LO + (uint32_t)(brow + p * 16) * PITCH + boff);
                bl[2 * p][0] = tmp[0]; bl[2 * p][1] = tmp[1];
                bl[2 * p + 1][0] = tmp[2]; bl[2 * p + 1][1] = tmp[3];
            }
            #pragma unroll
            for (int mt = 0; mt < 4; mt++)
                #pragma unroll
                for (int nt = 0; nt < 8; nt++) {
                    mma16816(acc[mt][nt], ah[mt], bh[nt]);
                    mma16816(acc[mt][nt], ah[mt], bl[nt]);
                    mma16816(acc[mt][nt], al[mt], bh[nt]);
                }
        }
    }

    #pragma unroll
    for (int mt = 0; mt < 4; mt++)
        #pragma unroll
        for (int nt = 0; nt < 8; nt++) {
            int mm = m0 + wm * 64 + mt * 16 + (l >> 2);
            int nn = n0 + wn * 64 + nt * 8 + (l & 3) * 2;
            size_t o0 = (size_t)mm * Cdim + nn;
            float2 xv = *(const float2*)(x + o0);
            float2 r0 = make_float2(xv.x + acc[mt][nt][0], xv.y + acc[mt][nt][1]);
            *(float2*)(g_y + o0) = r0;
            size_t o1 = o0 + (size_t)8 * Cdim;
            xv = *(const float2*)(x + o1);
            float2 r1 = make_float2(xv.x + acc[mt][nt][2], xv.y + acc[mt][nt][3]);
            *(float2*)(g_y + o1) = r1;
        }
}

// ---------------- LayerNorm + score + sumsq (warp-shuffle reductions) --------
__global__ void __launch_bounds__(256) k_ln(const float* __restrict__ gma,
                                            const float* __restrict__ bta,
                                            const float* __restrict__ sw,
                                            const float* __restrict__ sb) {
    __shared__ float red[16];
    __shared__ float bc[2];
    int row = blockIdx.x;
    const float* x = g_y + (size_t)row * Cdim;
    int t = threadIdx.x, wid = t >> 5, lid = t & 31;
    float v0 = x[t], v1 = x[t + 256], v2 = x[t + 512];
    float s1 = v0 + v1 + v2;
    float s2 = v0 * v0 + v1 * v1 + v2 * v2;
    #pragma unroll
    for (int o = 16; o; o >>= 1) {
        s1 += __shfl_xor_sync(0xffffffffu, s1, o);
        s2 += __shfl_xor_sync(0xffffffffu, s2, o);
    }
    if (lid == 0) { red[wid] = s1; red[8 + wid] = s2; }
    __syncthreads();
    if (wid == 0) {
        float a = (lid < 8) ? red[lid] : 0.f;
        float b = (lid < 8) ? red[8 + lid] : 0.f;
        #pragma unroll
        for (int o = 4; o; o >>= 1) {
            a += __shfl_xor_sync(0xffffffffu, a, o);
            b += __shfl_xor_sync(0xffffffffu, b, o);
        }
        if (lid == 0) {
            float mu = a * (1.f / Cdim);
            float var = b * (1.f / Cdim) - mu * mu;
            bc[0] = mu;
            bc[1] = rsqrtf(var + 1e-5f);
        }
    }
    __syncthreads();
    float mu = bc[0], rstd = bc[1];
    float y0 = (v0 - mu) * rstd * gma[t]       + bta[t];
    float y1 = (v1 - mu) * rstd * gma[t + 256] + bta[t + 256];
    float y2 = (v2 - mu) * rstd * gma[t + 512] + bta[t + 512];
    float* o = g_x2 + (size_t)row * Cdim;
    o[t] = y0; o[t + 256] = y1; o[t + 512] = y2;
    s1 = y0 * sw[t] + y1 * sw[t + 256] + y2 * sw[t + 512];
    s2 = y0 * y0 + y1 * y1 + y2 * y2;
    #pragma unroll
    for (int os = 16; os; os >>= 1) {
        s1 += __shfl_xor_sync(0xffffffffu, s1, os);
        s2 += __shfl_xor_sync(0xffffffffu, s2, os);
    }
    if (lid == 0) { red[wid] = s1; red[8 + wid] = s2; }
    __syncthreads();
    if (t == 0) {
        float a = 0.f, b = 0.f;
        #pragma unroll
        for (int i = 0; i < 8; i++) { a += red[i]; b += red[8 + i]; }
        g_tw[row] = expf(a + sb[0]);
        g_sq[row] = b;
    }
}

// ---------------- gram via HMMA -> distance matrix (triangle+mirror) --------
__device__ __forceinline__ void gemm_chunk(uint32_t st, int wm, int wn, int l,
                                           float acc[4][4][4]) {
    #pragma unroll
    for (int kh = 0; kh < 2; kh++) {
        uint32_t ah[4][4], al[4][4], bh[4][2], bl[4][2];
        uint32_t aoff = ((l >> 4) * 8 + kh * 16) * 2;
        int arow = wm * 64 + (l & 15);
        #pragma unroll
        for (int mt = 0; mt < 4; mt++) {
            ldm4(ah[mt], st + A_HI + (uint32_t)(arow + mt * 16) * PITCH + aoff);
            ldm4(al[mt], st + A_LO + (uint32_t)(arow + mt * 16) * PITCH + aoff);
        }
        int brow = wn * 32 + (l & 7) + ((l >> 4) & 1) * 8;
        uint32_t boff = (((l >> 3) & 1) * 8 + kh * 16) * 2;
        #pragma unroll
        for (int p = 0; p < 2; p++) {
            uint32_t tmp[4];
            ldm4(tmp, st + B_HI + (uint32_t)(brow + p * 16) * PITCH + boff);
            bh[2 * p][0] = tmp[0]; bh[2 * p][1] = tmp[1];
            bh[2 * p + 1][0] = tmp[2]; bh[2 * p + 1][1] = tmp[3];
            ldm4(tmp, st + B_LO + (uint32_t)(brow + p * 16) * PITCH + boff);
            bl[2 * p][0] = tmp[0]; bl[2 * p][1] = tmp[1];
            bl[2 * p + 1][0] = tmp[2]; bl[2 * p + 1][1] = tmp[3];
        }
        #pragma unroll
        for (int mt = 0; mt < 4; mt++)
            #pragma unroll
            for (int nt = 0; nt < 4; nt++) {
                mma16816(acc[mt][nt], ah[mt], bh[nt]);
                mma16816(acc[mt][nt], ah[mt], bl[nt]);
                mma16816(acc[mt][nt], al[mt], bh[nt]);
            }
    }
}

__device__ __forceinline__ void gram_load(uint32_t st, int r, int sg,
                                          int bz, int m0, int n0, int c) {
    int kc = c * 32;
    size_t ao = ((size_t)(bz * Ntok + m0 + r)) * Cdim + kc;
    size_t bo = ((size_t)(bz * Ntok + n0 + r)) * Cdim + kc;
    uint32_t ro = (uint32_t)r * PITCH;
    #pragma unroll
    for (int i = 0; i < 2; i++) {
        int seg = sg + i;
        uint32_t so = ro + seg * 16;
        cpa16(st + A_HI + so, g_xh + ao + seg * 8, 16);
        cpa16(st + A_LO + so, g_xl + ao + seg * 8, 16);
        cpa16(st + B_HI + so, g_xh + bo + seg * 8, 16);
        cpa16(st + B_LO + so, g_xl + bo + seg * 8, 16);
    }
    asm volatile("cp.async.commit_group;");
}

__global__ void __launch_bounds__(256) k_gram_mma() {
    extern __shared__ char sm[];
    uint32_t sb = smem_u32(sm);
    int t = threadIdx.x, l = t & 31, w = t >> 5;
    int wm = w & 1, wn = w >> 1;

    int rem = blockIdx.x, mi = 0;
    #pragma unroll 1
    while (rem >= 16 - mi) { rem -= 16 - mi; mi++; }
    int ni = mi + rem;
    const int bz = blockIdx.z;
    const int m0 = mi * 128, n0 = ni * 128;
    float* __restrict__ D = g_dist + (size_t)bz * Ntok * Ntok;
    const float* __restrict__ sqb = g_sq + bz * Ntok;
    int r = t >> 1, sg = (t & 1) * 2;

    float acc[4][4][4];
    #pragma unroll
    for (int i = 0; i < 4; i++)
        #pragma unroll
        for (int j = 0; j < 4; j++)
            #pragma unroll
            for (int q = 0; q < 4; q++) acc[i][j][q] = 0.f;

    const int C = 24;
    gram_load(sb, r, sg, bz, m0, n0, 0);
    for (int c = 0; c < C; c++) {
        asm volatile("cp.async.wait_group 0;");
        __syncthreads();
        if (c + 1 < C)
            gram_load(sb + ((c + 1) & 1) * STG, r, sg, bz, m0, n0, c + 1);
        gemm_chunk(sb + (c & 1) * STG, wm, wn, l, acc);
    }

    const float rs = rsqrtf((float)Cdim);
    #pragma unroll
    for (int mt = 0; mt < 4; mt++)
        #pragma unroll
        for (int nt = 0; nt < 4; nt++) {
            int mmb = m0 + wm * 64 + mt * 16 + (l >> 2);
            int nn = n0 + wn * 32 + nt * 8 + (l & 3) * 2;
            float s0 = sqb[nn], s1 = sqb[nn + 1];
            #pragma unroll
            for (int h = 0; h < 2; h++) {
                int M = mmb + h * 8;
                float sn = sqb[M];
                float d0 = sqrtf(fmaxf(sn + s0 - 2.f * acc[mt][nt][2 * h], 0.f)) * rs;
                float d1 = sqrtf(fmaxf(sn + s1 - 2.f * acc[mt][nt][2 * h + 1], 0.f)) * rs;
                *(float2*)(D + (size_t)M * Ntok + nn) = make_float2(d0, d1);
                if (ni > mi) {
                    D[(size_t)nn * Ntok + M]       = d0;
                    D[(size_t)(nn + 1) * Ntok + M] = d1;
                }
            }
        }
}

// ---------------- small helpers for scans -----------------------------------
__device__ __forceinline__ void ins3(float v, float& c0, float& c1, float& c2) {
    if (v < c2) {
        if (v < c1) {
            c2 = c1;
            if (v < c0) { c1 = c0; c0 = v; } else c1 = v;
        } else c2 = v;
    }
}

// ---------------- per-row: top-3 smallest + row max -> density --------------
__global__ void __launch_bounds__(256) k_top3(const float* __restrict__ noise) {
    int n = blockIdx.x, b = blockIdx.y;
    const float* row = g_dist + ((size_t)b * Ntok + n) * Ntok;
    int t = threadIdx.x;
    float c0 = 3e38f, c1 = 3e38f, c2 = 3e38f, mx = 0.f;
    for (int m = t; m < Ntok; m += 256) {
        float v = row[m];
        mx = fmaxf(mx, v);
        ins3(v, c0, c1, c2);
    }
    __shared__ float s0[256], s1[256], s2[256], smx[256];
    s0[t] = c0; s1[t] = c1; s2[t] = c2; smx[t] = mx;
    __syncthreads();
    for (int h = 128; h; h >>= 1) {
        if (t < h) {
            float b0 = s0[t + h], b1 = s1[t + h], b2 = s2[t + h];
            c0 = s0[t]; c1 = s1[t]; c2 = s2[t];
            ins3(b0, c0, c1, c2); ins3(b1, c0, c1, c2); ins3(b2, c0, c1, c2);
            s0[t] = c0; s1[t] = c1; s2[t] = c2;
            smx[t] = fmaxf(smx[t], smx[t + h]);
        }
        __syncthreads();
    }
    if (t == 0) {
        float m3 = (s0[0] * s0[0] + s1[0] * s1[0] + s2[0] * s2[0]) * (1.f / 3.f);
        g_den[b * Ntok + n] = expf(-m3) + noise[b * Ntok + n] * 1e-6f;
        atomicMax((int*)&g_dmax[b], __float_as_int(smx[0]));
    }
}

// ---------------- per-row: dist to nearest higher-density -> score ----------
__global__ void __launch_bounds__(256) k_dmin() {
    int n = blockIdx.x, b = blockIdx.y;
    const float* row = g_dist + ((size_t)b * Ntok + n) * Ntok;
    const float* den = g_den + b * Ntok;
    float dn = den[n];
    float dmax = g_dmax[b];
    int t = threadIdx.x;
    float mn = 3e38f;
    for (int m = t; m < Ntok; m += 256) {
        float v = (den[m] > dn) ? row[m] : dmax;
        mn = fminf(mn, v);
    }
    __shared__ float s[256];
    s[t] = mn; __syncthreads();
    for (int h = 128; h; h >>= 1) {
        if (t < h) s[t] = fminf(s[t], s[t + h]);
        __syncthreads();
    }
    if (t == 0) g_sc[b * Ntok + n] = s[0] * dn;
}

// ---------------- per-batch: top-2 score indices ----------------------------
__global__ void __launch_bounds__(256) k_top2() {
    int b = blockIdx.x, t = threadIdx.x;
    const float* sc = g_sc + b * Ntok;
    __shared__ float bv[256];
    __shared__ int   bi[256];
    float v = -3e38f; int ii = 0x7fffffff;
    for (int m = t; m < Ntok; m += 256) {
        float x = sc[m];
        if (x > v) { v = x; ii = m; }
    }
    bv[t] = v; bi[t] = ii; __syncthreads();
    for (int h = 128; h; h >>= 1) {
        if (t < h) {
            if (bv[t + h] > bv[t] || (bv[t + h] == bv[t] && bi[t + h] < bi[t])) {
                bv[t] = bv[t + h]; bi[t] = bi[t + h];
            }
        }
        __syncthreads();
    }
    int i0 = bi[0];
    __syncthreads();
    v = -3e38f; ii = 0x7fffffff;
    for (int m = t; m < Ntok; m += 256) {
        if (m == i0) continue;
        float x = sc[m];
        if (x > v) { v = x; ii = m; }
    }
    bv[t] = v; bi[t] = ii; __syncthreads();
    for (int h = 128; h; h >>= 1) {
        if (t < h) {
            if (bv[t + h] > bv[t] || (bv[t + h] == bv[t] && bi[t + h] < bi[t])) {
                bv[t] = bv[t + h]; bi[t] = bi[t + h];
            }
        }
        __syncthreads();
    }
    if (t == 0) {
        g_idn[2 * b]     = i0;
        g_idn[2 * b + 1] = bi[0];
        g_aw[2 * b]      = 1e-6f;
        g_aw[2 * b + 1]  = 1e-6f;
    }
}

// ---------------- assign clusters + accumulate cluster weights --------------
__global__ void __launch_bounds__(256) k_assign() {
    int tk = blockIdx.x * 256 + threadIdx.x;
    int b = tk >> 11, n = tk & (Ntok - 1);
    int i0 = g_idn[2 * b], i1 = g_idn[2 * b + 1];
    float d0 = g_dist[((size_t)b * Ntok + i0) * Ntok + n];
    float d1 = g_dist[((size_t)b * Ntok + i1) * Ntok + n];
    int cl = (d1 < d0) ? 1 : 0;
    if (n == i0) cl = 0;
    if (n == i1) cl = 1;
    g_cl[tk] = cl;
    float w = g_tw[tk];
    float w0 = cl ? 0.f : w;
    float w1 = cl ? w : 0.f;
    #pragma unroll
    for (int o = 16; o; o >>= 1) {
        w0 += __shfl_down_sync(0xffffffffu, w0, o);
        w1 += __shfl_down_sync(0xffffffffu, w1, o);
    }
    if ((threadIdx.x & 31) == 0) {
        atomicAdd(&g_aw[2 * b],     w0);
        atomicAdd(&g_aw[2 * b + 1], w1);
    }
}

// ---------------- normalized weights + aux outputs --------------------------
__global__ void __launch_bounds__(256) k_norm(float* __restrict__ out, int out_size) {
    int tk = blockIdx.x * 256 + threadIdx.x;
    int b = tk >> 11;
    int cl = g_cl[tk];
    float nw = g_tw[tk] / g_aw[2 * b + cl];
    g_nw[tk] = nw;
    const int XM = Bsz * 2 * Cdim;       // 24576
    if (out_size >= XM + BN)       out[XM + tk]      = nw;
    if (out_size >= XM + 2 * BN)   out[XM + BN + tk] = (float)cl;
}

// ---------------- zero merged-x slab, then parallel weighted merge ----------
__global__ void __launch_bounds__(128) k_zero(float* __restrict__ out) {
    int i = blockIdx.x * 128 + threadIdx.x;
    if (i < Bsz * 2 * Cdim) out[i] = 0.f;
}

__global__ void __launch_bounds__(128) k_merge(float* __restrict__ out) {
    int b = blockIdx.y;
    int c = blockIdx.x * 128 + threadIdx.x;
    int n0 = blockIdx.z * 256;
    const float* X  = g_x2 + ((size_t)b * Ntok + n0) * Cdim + c;
    const float* nw = g_nw + b * Ntok + n0;
    const int*   cl = g_cl + b * Ntok + n0;
    float a0 = 0.f, a1 = 0.f;
    for (int n = 0; n < 256; n++) {
        float w  = nw[n];
        float xv = X[(size_t)n * Cdim];
        if (cl[n] == 0) a0 = fmaf(xv, w, a0);
        else            a1 = fmaf(xv, w, a1);
    }
    atomicAdd(&out[((size_t)b * 2 + 0) * Cdim + c], a0);
    atomicAdd(&out[((size_t)b * 2 + 1) * Cdim + c], a1);
}

// ---------------- launch ----------------------------------------------------
extern "C" void kernel_launch(void* const* d_in, const int* in_sizes, int n_in,
                              void* d_out, int out_size) {
    const float* x     = (const float*)d_in[0];
    const float* cw    = (const float*)d_in[1];
    const float* gma   = (const float*)d_in[2];
    const float* bta   = (const float*)d_in[3];
    const float* sw    = (const float*)d_in[4];
    const float* sb    = (const float*)d_in[5];
    const float* noise = (const float*)d_in[6];
    float* out = (float*)d_out;

    cudaFuncSetAttribute(k_conv_mma, cudaFuncAttributeMaxDynamicSharedMemorySize, SMEM_CONV);
    cudaFuncSetAttribute(k_gram_mma, cudaFuncAttributeMaxDynamicSharedMemorySize, SMEM_DYN);

    k_init<<<1, 32>>>();
    k_splitw<<<(3 * Cdim * Cdim + 255) / 256, 256>>>(cw);
    k_split_in<<<(BN * Cdim / 4) / 256, 256>>>(x);

    dim3 gc(Cdim / 256, BN / 128);      // (3, 256)
    k_conv_mma<<<gc, 256, SMEM_CONV>>>(x);

    k_ln<<<BN, 256>>>(gma, bta, sw, sb);
    k_split_x2<<<(BN * Cdim / 4) / 256, 256>>>();

    dim3 gg(136, 1, Bsz);               // upper-triangle tiles x batches
    k_gram_mma<<<gg, 256, SMEM_DYN>>>();

    dim3 gr(Ntok, Bsz);
    k_top3<<<gr, 256>>>(noise);
    k_dmin<<<gr, 256>>>();
    k_top2<<<Bsz, 256>>>();
    k_assign<<<BN / 256, 256>>>();
    k_norm<<<BN / 256, 256>>>(out, out_size);
    k_zero<<<(Bsz * 2 * Cdim + 127) / 128, 128>>>(out);
    dim3 gm(Cdim / 128, Bsz, Ntok / 256);   // (6, 16, 8)
    k_merge<<<gm, 128>>>(out);
}

// round 17
// speedup vs baseline: 1.1297x; 1.1297x over previous
#include <cuda_runtime.h>
#include <cuda_bf16.h>
#include <math.h>
#include <stdint.h>

#define Bsz  16
#define Ntok 2048
#define Cdim 768
#define BN   (Bsz*Ntok)

// ---------------- scratch (static device globals; no allocation) ------------
__device__ float g_y [(size_t)BN*Cdim];                 // conv+residual output
__device__ float g_x2[(size_t)BN*Cdim];                 // layernormed x
__device__ __align__(16) __nv_bfloat16 g_xh[(size_t)BN*Cdim];   // hi split
__device__ __align__(16) __nv_bfloat16 g_xl[(size_t)BN*Cdim];   // lo split
__device__ __align__(16) __nv_bfloat16 g_wh[3*Cdim*Cdim];       // W hi [tap][co][ci]
__device__ __align__(16) __nv_bfloat16 g_wl[3*Cdim*Cdim];       // W lo
__device__ float g_dist[(size_t)Bsz*Ntok*Ntok];         // 268 MB distance matrix
__device__ float g_tw [BN];
__device__ float g_sq [BN];
__device__ float g_den[BN];
__device__ float g_sc [BN];
__device__ float g_dmax[Bsz];
__device__ int   g_idn[Bsz*2];
__device__ float g_aw [Bsz*2];
__device__ int   g_cl [BN];
__device__ float g_nw [BN];

// ---------------- mma/ldmatrix/cp.async helpers ------------------------------
__device__ __forceinline__ uint32_t smem_u32(const void* p) {
    uint32_t a;
    asm("{ .reg .u64 t; cvta.to.shared.u64 t, %1; cvt.u32.u64 %0, t; }"
        : "=r"(a) : "l"(p));
    return a;
}

__device__ __forceinline__ void cpa16(uint32_t d, const void* s, int sz) {
    asm volatile("cp.async.cg.shared.global [%0], [%1], 16, %2;"
                 :: "r"(d), "l"(s), "r"(sz));
}

__device__ __forceinline__ void ldm4(uint32_t* r, uint32_t a) {
    asm volatile("ldmatrix.sync.aligned.m8n8.x4.shared.b16 {%0,%1,%2,%3}, [%4];"
                 : "=r"(r[0]), "=r"(r[1]), "=r"(r[2]), "=r"(r[3]) : "r"(a));
}

__device__ __forceinline__ void mma16816(float* c, const uint32_t* a, const uint32_t* b) {
    asm volatile(
        "mma.sync.aligned.m16n8k16.row.col.f32.bf16.bf16.f32 "
        "{%0,%1,%2,%3}, {%4,%5,%6,%7}, {%8,%9}, {%0,%1,%2,%3};"
        : "+f"(c[0]), "+f"(c[1]), "+f"(c[2]), "+f"(c[3])
        : "r"(a[0]), "r"(a[1]), "r"(a[2]), "r"(a[3]), "r"(b[0]), "r"(b[1]));
}

// ---- gram smem geometry: 4 matrices of 128 rows x 32 bf16, pitch 80B, 2 stg
#define PITCH 80
#define MATB  (128*PITCH)     // 10240
#define A_HI  0
#define A_LO  (1*MATB)
#define B_HI  (2*MATB)
#define B_LO  (3*MATB)
#define STG   (4*MATB)        // 40960
#define SMEM_DYN (2*STG)      // 81920

// ---- conv smem geometry: A 256 rows, B 128 rows, pitch 80B, 2 stages --------
#define A2_HI 0
#define A2_LO (256*PITCH)                 // 20480
#define B2_HI (2*256*PITCH)               // 40960
#define B2_LO (2*256*PITCH + 128*PITCH)   // 51200
#define STG2  (2*256*PITCH + 2*128*PITCH) // 61440
#define SMEM_CONV (2*STG2)                // 122880

// ---------------- misc small kernels ----------------------------------------
__global__ void k_init() {
    int t = threadIdx.x;
    if (t < Bsz) g_dmax[t] = 0.0f;
}

__global__ void k_splitw(const float* __restrict__ w) {
    int i = blockIdx.x * 256 + threadIdx.x;
    if (i >= 3 * Cdim * Cdim) return;
    int ci = i % Cdim;
    int co = (i / Cdim) % Cdim;
    int k  = i / (Cdim * Cdim);
    float v = w[((size_t)co * Cdim + ci) * 3 + k];
    __nv_bfloat16 h = __float2bfloat16(v);
    g_wh[i] = h;
    g_wl[i] = __float2bfloat16(v - __bfloat162float(h));
}

__global__ void __launch_bounds__(256) k_split_in(const float* __restrict__ src) {
    size_t i = ((size_t)blockIdx.x * 256 + threadIdx.x) * 4;
    float4 v = *(const float4*)(src + i);
    __nv_bfloat16 h0 = __float2bfloat16(v.x), h1 = __float2bfloat16(v.y);
    __nv_bfloat16 h2 = __float2bfloat16(v.z), h3 = __float2bfloat16(v.w);
    __nv_bfloat162* ph = (__nv_bfloat162*)(g_xh + i);
    __nv_bfloat162* pl = (__nv_bfloat162*)(g_xl + i);
    ph[0] = __nv_bfloat162(h0, h1);
    ph[1] = __nv_bfloat162(h2, h3);
    pl[0] = __nv_bfloat162(__float2bfloat16(v.x - __bfloat162float(h0)),
                           __float2bfloat16(v.y - __bfloat162float(h1)));
    pl[1] = __nv_bfloat162(__float2bfloat16(v.z - __bfloat162float(h2)),
                           __float2bfloat16(v.w - __bfloat162float(h3)));
}

// ================== CONV: block 256x128, 512 thr, warp tile 64x32 ============
__device__ __forceinline__ void conv_load2(uint32_t st, int t, int m0, int n0, int c) {
    int tap = c / 24, kc = (c % 24) * 32;
    // A: 256 rows, 2 segs/thread per matrix (512 thr x 2 = 1024 segs = 256r x 4)
    {
        int r = t >> 1, sg = (t & 1) * 2;
        int m = m0 + r;
        int loc = (m & (Ntok - 1)) + tap - 1;
        bool v = (loc >= 0 && loc < Ntok);
        long long ao = (long long)(m + tap - 1) * Cdim + kc;
        uint32_t ro = (uint32_t)r * PITCH;
        #pragma unroll
        for (int i = 0; i < 2; i++) {
            int seg = sg + i;
            uint32_t so = ro + seg * 16;
            cpa16(st + A2_HI + so, v ? (const void*)(g_xh + ao + seg * 8) : (const void*)g_xh, v ? 16 : 0);
            cpa16(st + A2_LO + so, v ? (const void*)(g_xl + ao + seg * 8) : (const void*)g_xl, v ? 16 : 0);
        }
    }
    // B: 128 rows, 1 seg/thread per matrix (512 thr = 128r x 4segs)
    {
        int r = t >> 2, sg = t & 3;
        size_t wo = ((size_t)tap * Cdim + n0 + r) * Cdim + kc;
        uint32_t so = (uint32_t)r * PITCH + sg * 16;
        cpa16(st + B2_HI + so, g_wh + wo + sg * 8, 16);
        cpa16(st + B2_LO + so, g_wl + wo + sg * 8, 16);
    }
    asm volatile("cp.async.commit_group;");
}

__global__ void __launch_bounds__(512) k_conv_mma(const float* __restrict__ x) {
    extern __shared__ char sm[];
    uint32_t sb = smem_u32(sm);
    int t = threadIdx.x, l = t & 31, w = t >> 5;
    int wm = w & 3, wn = w >> 2;           // 4 x 4 warp grid, 64x32 per warp
    int m0 = blockIdx.y * 256, n0 = blockIdx.x * 128;

    float acc[4][4][4];
    #pragma unroll
    for (int i = 0; i < 4; i++)
        #pragma unroll
        for (int j = 0; j < 4; j++)
            #pragma unroll
            for (int q = 0; q < 4; q++) acc[i][j][q] = 0.f;

    const int C = 72;
    conv_load2(sb, t, m0, n0, 0);
    for (int c = 0; c < C; c++) {
        asm volatile("cp.async.wait_group 0;");
        __syncthreads();
        if (c + 1 < C)
            conv_load2(sb + ((c + 1) & 1) * STG2, t, m0, n0, c + 1);
        uint32_t st = sb + (c & 1) * STG2;
        #pragma unroll
        for (int kh = 0; kh < 2; kh++) {
            uint32_t ah[4][4], al[4][4], bh[4][2], bl[4][2];
            uint32_t aoff = ((l >> 4) * 8 + kh * 16) * 2;
            int arow = wm * 64 + (l & 15);
            #pragma unroll
            for (int mt = 0; mt < 4; mt++) {
                ldm4(ah[mt], st + A2_HI + (uint32_t)(arow + mt * 16) * PITCH + aoff);
                ldm4(al[mt], st + A2_LO + (uint32_t)(arow + mt * 16) * PITCH + aoff);
            }
            int brow = wn * 32 + (l & 7) + ((l >> 4) & 1) * 8;
            uint32_t boff = (((l >> 3) & 1) * 8 + kh * 16) * 2;
            #pragma unroll
            for (int p = 0; p < 2; p++) {
                uint32_t tmp[4];
                ldm4(tmp, st + B2_HI + (uint32_t)(brow + p * 16) * PITCH + boff);
                bh[2 * p][0] = tmp[0]; bh[2 * p][1] = tmp[1];
                bh[2 * p + 1][0] = tmp[2]; bh[2 * p + 1][1] = tmp[3];
                ldm4(tmp, st + B2_LO + (uint32_t)(brow + p * 16) * PITCH + boff);
                bl[2 * p][0] = tmp[0]; bl[2 * p][1] = tmp[1];
                bl[2 * p + 1][0] = tmp[2]; bl[2 * p + 1][1] = tmp[3];
            }
            #pragma unroll
            for (int mt = 0; mt < 4; mt++)
                #pragma unroll
                for (int nt = 0; nt < 4; nt++) {
                    mma16816(acc[mt][nt], ah[mt], bh[nt]);
                    mma16816(acc[mt][nt], ah[mt], bl[nt]);
                    mma16816(acc[mt][nt], al[mt], bh[nt]);
                }
        }
    }

    #pragma unroll
    for (int mt = 0; mt < 4; mt++)
        #pragma unroll
        for (int nt = 0; nt < 4; nt++) {
            int mm = m0 + wm * 64 + mt * 16 + (l >> 2);
            int nn = n0 + wn * 32 + nt * 8 + (l & 3) * 2;
            size_t o0 = (size_t)mm * Cdim + nn;
            float2 xv = *(const float2*)(x + o0);
            float2 r0 = make_float2(xv.x + acc[mt][nt][0], xv.y + acc[mt][nt][1]);
            *(float2*)(g_y + o0) = r0;
            size_t o1 = o0 + (size_t)8 * Cdim;
            xv = *(const float2*)(x + o1);
            float2 r1 = make_float2(xv.x + acc[mt][nt][2], xv.y + acc[mt][nt][3]);
            *(float2*)(g_y + o1) = r1;
        }
}

// ------- LayerNorm + score + sumsq + fused hi/lo split (shuffle red.) --------
__global__ void __launch_bounds__(256) k_ln(const float* __restrict__ gma,
                                            const float* __restrict__ bta,
                                            const float* __restrict__ sw,
                                            const float* __restrict__ sb) {
    __shared__ float red[16];
    __shared__ float bc[2];
    int row = blockIdx.x;
    const float* x = g_y + (size_t)row * Cdim;
    int t = threadIdx.x, wid = t >> 5, lid = t & 31;
    float v0 = x[t], v1 = x[t + 256], v2 = x[t + 512];
    float s1 = v0 + v1 + v2;
    float s2 = v0 * v0 + v1 * v1 + v2 * v2;
    #pragma unroll
    for (int o = 16; o; o >>= 1) {
        s1 += __shfl_xor_sync(0xffffffffu, s1, o);
        s2 += __shfl_xor_sync(0xffffffffu, s2, o);
    }
    if (lid == 0) { red[wid] = s1; red[8 + wid] = s2; }
    __syncthreads();
    if (wid == 0) {
        float a = (lid < 8) ? red[lid] : 0.f;
        float b = (lid < 8) ? red[8 + lid] : 0.f;
        #pragma unroll
        for (int o = 4; o; o >>= 1) {
            a += __shfl_xor_sync(0xffffffffu, a, o);
            b += __shfl_xor_sync(0xffffffffu, b, o);
        }
        if (lid == 0) {
            float mu = a * (1.f / Cdim);
            float var = b * (1.f / Cdim) - mu * mu;
            bc[0] = mu;
            bc[1] = rsqrtf(var + 1e-5f);
        }
    }
    __syncthreads();
    float mu = bc[0], rstd = bc[1];
    float y0 = (v0 - mu) * rstd * gma[t]       + bta[t];
    float y1 = (v1 - mu) * rstd * gma[t + 256] + bta[t + 256];
    float y2 = (v2 - mu) * rstd * gma[t + 512] + bta[t + 512];
    float* o = g_x2 + (size_t)row * Cdim;
    o[t] = y0; o[t + 256] = y1; o[t + 512] = y2;
    // fused hi/lo split (replaces k_split_x2)
    {
        __nv_bfloat16* xh = g_xh + (size_t)row * Cdim;
        __nv_bfloat16* xl = g_xl + (size_t)row * Cdim;
        __nv_bfloat16 h0 = __float2bfloat16(y0);
        __nv_bfloat16 h1 = __float2bfloat16(y1);
        __nv_bfloat16 h2 = __float2bfloat16(y2);
        xh[t] = h0; xh[t + 256] = h1; xh[t + 512] = h2;
        xl[t]       = __float2bfloat16(y0 - __bfloat162float(h0));
        xl[t + 256] = __float2bfloat16(y1 - __bfloat162float(h1));
        xl[t + 512] = __float2bfloat16(y2 - __bfloat162float(h2));
    }
    s1 = y0 * sw[t] + y1 * sw[t + 256] + y2 * sw[t + 512];
    s2 = y0 * y0 + y1 * y1 + y2 * y2;
    #pragma unroll
    for (int os = 16; os; os >>= 1) {
        s1 += __shfl_xor_sync(0xffffffffu, s1, os);
        s2 += __shfl_xor_sync(0xffffffffu, s2, os);
    }
    if (lid == 0) { red[wid] = s1; red[8 + wid] = s2; }
    __syncthreads();
    if (t == 0) {
        float a = 0.f, b = 0.f;
        #pragma unroll
        for (int i = 0; i < 8; i++) { a += red[i]; b += red[8 + i]; }
        g_tw[row] = expf(a + sb[0]);
        g_sq[row] = b;
    }
}

// ---------------- gram via HMMA -> distance matrix (triangle+mirror) --------
__device__ __forceinline__ void gemm_chunk(uint32_t st, int wm, int wn, int l,
                                           float acc[4][4][4]) {
    #pragma unroll
    for (int kh = 0; kh < 2; kh++) {
        uint32_t ah[4][4], al[4][4], bh[4][2], bl[4][2];
        uint32_t aoff = ((l >> 4) * 8 + kh * 16) * 2;
        int arow = wm * 64 + (l & 15);
        #pragma unroll
        for (int mt = 0; mt < 4; mt++) {
            ldm4(ah[mt], st + A_HI + (uint32_t)(arow + mt * 16) * PITCH + aoff);
            ldm4(al[mt], st + A_LO + (uint32_t)(arow + mt * 16) * PITCH + aoff);
        }
        int brow = wn * 32 + (l & 7) + ((l >> 4) & 1) * 8;
        uint32_t boff = (((l >> 3) & 1) * 8 + kh * 16) * 2;
        #pragma unroll
        for (int p = 0; p < 2; p++) {
            uint32_t tmp[4];
            ldm4(tmp, st + B_HI + (uint32_t)(brow + p * 16) * PITCH + boff);
            bh[2 * p][0] = tmp[0]; bh[2 * p][1] = tmp[1];
            bh[2 * p + 1][0] = tmp[2]; bh[2 * p + 1][1] = tmp[3];
            ldm4(tmp, st + B_LO + (uint32_t)(brow + p * 16) * PITCH + boff);
            bl[2 * p][0] = tmp[0]; bl[2 * p][1] = tmp[1];
            bl[2 * p + 1][0] = tmp[2]; bl[2 * p + 1][1] = tmp[3];
        }
        #pragma unroll
        for (int mt = 0; mt < 4; mt++)
            #pragma unroll
            for (int nt = 0; nt < 4; nt++) {
                mma16816(acc[mt][nt], ah[mt], bh[nt]);
                mma16816(acc[mt][nt], ah[mt], bl[nt]);
                mma16816(acc[mt][nt], al[mt], bh[nt]);
            }
    }
}

__device__ __forceinline__ void gram_load(uint32_t st, int r, int sg,
                                          int bz, int m0, int n0, int c) {
    int kc = c * 32;
    size_t ao = ((size_t)(bz * Ntok + m0 + r)) * Cdim + kc;
    size_t bo = ((size_t)(bz * Ntok + n0 + r)) * Cdim + kc;
    uint32_t ro = (uint32_t)r * PITCH;
    #pragma unroll
    for (int i = 0; i < 2; i++) {
        int seg = sg + i;
        uint32_t so = ro + seg * 16;
        cpa16(st + A_HI + so, g_xh + ao + seg * 8, 16);
        cpa16(st + A_LO + so, g_xl + ao + seg * 8, 16);
        cpa16(st + B_HI + so, g_xh + bo + seg * 8, 16);
        cpa16(st + B_LO + so, g_xl + bo + seg * 8, 16);
    }
    asm volatile("cp.async.commit_group;");
}

__global__ void __launch_bounds__(256) k_gram_mma() {
    extern __shared__ char sm[];
    uint32_t sb = smem_u32(sm);
    int t = threadIdx.x, l = t & 31, w = t >> 5;
    int wm = w & 1, wn = w >> 1;

    int rem = blockIdx.x, mi = 0;
    #pragma unroll 1
    while (rem >= 16 - mi) { rem -= 16 - mi; mi++; }
    int ni = mi + rem;
    const int bz = blockIdx.z;
    const int m0 = mi * 128, n0 = ni * 128;
    float* __restrict__ D = g_dist + (size_t)bz * Ntok * Ntok;
    const float* __restrict__ sqb = g_sq + bz * Ntok;
    int r = t >> 1, sg = (t & 1) * 2;

    float acc[4][4][4];
    #pragma unroll
    for (int i = 0; i < 4; i++)
        #pragma unroll
        for (int j = 0; j < 4; j++)
            #pragma unroll
            for (int q = 0; q < 4; q++) acc[i][j][q] = 0.f;

    const int C = 24;
    gram_load(sb, r, sg, bz, m0, n0, 0);
    for (int c = 0; c < C; c++) {
        asm volatile("cp.async.wait_group 0;");
        __syncthreads();
        if (c + 1 < C)
            gram_load(sb + ((c + 1) & 1) * STG, r, sg, bz, m0, n0, c + 1);
        gemm_chunk(sb + (c & 1) * STG, wm, wn, l, acc);
    }

    const float rs = rsqrtf((float)Cdim);
    #pragma unroll
    for (int mt = 0; mt < 4; mt++)
        #pragma unroll
        for (int nt = 0; nt < 4; nt++) {
            int mmb = m0 + wm * 64 + mt * 16 + (l >> 2);
            int nn = n0 + wn * 32 + nt * 8 + (l & 3) * 2;
            float s0 = sqb[nn], s1 = sqb[nn + 1];
            #pragma unroll
            for (int h = 0; h < 2; h++) {
                int M = mmb + h * 8;
                float sn = sqb[M];
                float d0 = sqrtf(fmaxf(sn + s0 - 2.f * acc[mt][nt][2 * h], 0.f)) * rs;
                float d1 = sqrtf(fmaxf(sn + s1 - 2.f * acc[mt][nt][2 * h + 1], 0.f)) * rs;
                *(float2*)(D + (size_t)M * Ntok + nn) = make_float2(d0, d1);
                if (ni > mi) {
                    D[(size_t)nn * Ntok + M]       = d0;
                    D[(size_t)(nn + 1) * Ntok + M] = d1;
                }
            }
        }
}

// ---------------- small helpers for scans -----------------------------------
__device__ __forceinline__ void ins3(float v, float& c0, float& c1, float& c2) {
    if (v < c2) {
        if (v < c1) {
            c2 = c1;
            if (v < c0) { c1 = c0; c0 = v; } else c1 = v;
        } else c2 = v;
    }
}

// ---------------- per-row: top-3 smallest + row max -> density --------------
__global__ void __launch_bounds__(256) k_top3(const float* __restrict__ noise) {
    int n = blockIdx.x, b = blockIdx.y;
    const float* row = g_dist + ((size_t)b * Ntok + n) * Ntok;
    int t = threadIdx.x;
    float c0 = 3e38f, c1 = 3e38f, c2 = 3e38f, mx = 0.f;
    for (int m = t; m < Ntok; m += 256) {
        float v = row[m];
        mx = fmaxf(mx, v);
        ins3(v, c0, c1, c2);
    }
    __shared__ float s0[256], s1[256], s2[256], smx[256];
    s0[t] = c0; s1[t] = c1; s2[t] = c2; smx[t] = mx;
    __syncthreads();
    for (int h = 128; h; h >>= 1) {
        if (t < h) {
            float b0 = s0[t + h], b1 = s1[t + h], b2 = s2[t + h];
            c0 = s0[t]; c1 = s1[t]; c2 = s2[t];
            ins3(b0, c0, c1, c2); ins3(b1, c0, c1, c2); ins3(b2, c0, c1, c2);
            s0[t] = c0; s1[t] = c1; s2[t] = c2;
            smx[t] = fmaxf(smx[t], smx[t + h]);
        }
        __syncthreads();
    }
    if (t == 0) {
        float m3 = (s0[0] * s0[0] + s1[0] * s1[0] + s2[0] * s2[0]) * (1.f / 3.f);
        g_den[b * Ntok + n] = expf(-m3) + noise[b * Ntok + n] * 1e-6f;
        atomicMax((int*)&g_dmax[b], __float_as_int(smx[0]));
    }
}

// ---------------- per-row: dist to nearest higher-density -> score ----------
__global__ void __launch_bounds__(256) k_dmin() {
    int n = blockIdx.x, b = blockIdx.y;
    const float* row = g_dist + ((size_t)b * Ntok + n) * Ntok;
    const float* den = g_den + b * Ntok;
    float dn = den[n];
    float dmax = g_dmax[b];
    int t = threadIdx.x;
    float mn = 3e38f;
    for (int m = t; m < Ntok; m += 256) {
        float v = (den[m] > dn) ? row[m] : dmax;
        mn = fminf(mn, v);
    }
    __shared__ float s[256];
    s[t] = mn; __syncthreads();
    for (int h = 128; h; h >>= 1) {
        if (t < h) s[t] = fminf(s[t], s[t + h]);
        __syncthreads();
    }
    if (t == 0) g_sc[b * Ntok + n] = s[0] * dn;
}

// ---------------- per-batch: top-2 score indices ----------------------------
__global__ void __launch_bounds__(256) k_top2() {
    int b = blockIdx.x, t = threadIdx.x;
    const float* sc = g_sc + b * Ntok;
    __shared__ float bv[256];
    __shared__ int   bi[256];
    float v = -3e38f; int ii = 0x7fffffff;
    for (int m = t; m < Ntok; m += 256) {
        float x = sc[m];
        if (x > v) { v = x; ii = m; }
    }
    bv[t] = v; bi[t] = ii; __syncthreads();
    for (int h = 128; h; h >>= 1) {
        if (t < h) {
            if (bv[t + h] > bv[t] || (bv[t + h] == bv[t] && bi[t + h] < bi[t])) {
                bv[t] = bv[t + h]; bi[t] = bi[t + h];
            }
        }
        __syncthreads();
    }
    int i0 = bi[0];
    __syncthreads();
    v = -3e38f; ii = 0x7fffffff;
    for (int m = t; m < Ntok; m += 256) {
        if (m == i0) continue;
        float x = sc[m];
        if (x > v) { v = x; ii = m; }
    }
    bv[t] = v; bi[t] = ii; __syncthreads();
    for (int h = 128; h; h >>= 1) {
        if (t < h) {
            if (bv[t + h] > bv[t] || (bv[t + h] == bv[t] && bi[t + h] < bi[t])) {
                bv[t] = bv[t + h]; bi[t] = bi[t + h];
            }
        }
        __syncthreads();
    }
    if (t == 0) {
        g_idn[2 * b]     = i0;
        g_idn[2 * b + 1] = bi[0];
        g_aw[2 * b]      = 1e-6f;
        g_aw[2 * b + 1]  = 1e-6f;
    }
}

// ---------------- assign clusters + accumulate cluster weights --------------
__global__ void __launch_bounds__(256) k_assign() {
    int tk = blockIdx.x * 256 + threadIdx.x;
    int b = tk >> 11, n = tk & (Ntok - 1);
    int i0 = g_idn[2 * b], i1 = g_idn[2 * b + 1];
    float d0 = g_dist[((size_t)b * Ntok + i0) * Ntok + n];
    float d1 = g_dist[((size_t)b * Ntok + i1) * Ntok + n];
    int cl = (d1 < d0) ? 1 : 0;
    if (n == i0) cl = 0;
    if (n == i1) cl = 1;
    g_cl[tk] = cl;
    float w = g_tw[tk];
    float w0 = cl ? 0.f : w;
    float w1 = cl ? w : 0.f;
    #pragma unroll
    for (int o = 16; o; o >>= 1) {
        w0 += __shfl_down_sync(0xffffffffu, w0, o);
        w1 += __shfl_down_sync(0xffffffffu, w1, o);
    }
    if ((threadIdx.x & 31) == 0) {
        atomicAdd(&g_aw[2 * b],     w0);
        atomicAdd(&g_aw[2 * b + 1], w1);
    }
}

// ---------------- normalized weights + aux outputs --------------------------
__global__ void __launch_bounds__(256) k_norm(float* __restrict__ out, int out_size) {
    int tk = blockIdx.x * 256 + threadIdx.x;
    int b = tk >> 11;
    int cl = g_cl[tk];
    float nw = g_tw[tk] / g_aw[2 * b + cl];
    g_nw[tk] = nw;
    const int XM = Bsz * 2 * Cdim;       // 24576
    if (out_size >= XM + BN)       out[XM + tk]      = nw;
    if (out_size >= XM + 2 * BN)   out[XM + BN + tk] = (float)cl;
}

// ---------------- zero merged-x slab, then parallel weighted merge ----------
__global__ void __launch_bounds__(128) k_zero(float* __restrict__ out) {
    int i = blockIdx.x * 128 + threadIdx.x;
    if (i < Bsz * 2 * Cdim) out[i] = 0.f;
}

__global__ void __launch_bounds__(128) k_merge(float* __restrict__ out) {
    int b = blockIdx.y;
    int c = blockIdx.x * 128 + threadIdx.x;
    int n0 = blockIdx.z * 256;
    const float* X  = g_x2 + ((size_t)b * Ntok + n0) * Cdim + c;
    const float* nw = g_nw + b * Ntok + n0;
    const int*   cl = g_cl + b * Ntok + n0;
    float a0 = 0.f, a1 = 0.f;
    for (int n = 0; n < 256; n++) {
        float w  = nw[n];
        float xv = X[(size_t)n * Cdim];
        if (cl[n] == 0) a0 = fmaf(xv, w, a0);
        else            a1 = fmaf(xv, w, a1);
    }
    atomicAdd(&out[((size_t)b * 2 + 0) * Cdim + c], a0);
    atomicAdd(&out[((size_t)b * 2 + 1) * Cdim + c], a1);
}

// ---------------- launch ----------------------------------------------------
extern "C" void kernel_launch(void* const* d_in, const int* in_sizes, int n_in,
                              void* d_out, int out_size) {
    const float* x     = (const float*)d_in[0];
    const float* cw    = (const float*)d_in[1];
    const float* gma   = (const float*)d_in[2];
    const float* bta   = (const float*)d_in[3];
    const float* sw    = (const float*)d_in[4];
    const float* sb    = (const float*)d_in[5];
    const float* noise = (const float*)d_in[6];
    float* out = (float*)d_out;

    cudaFuncSetAttribute(k_conv_mma, cudaFuncAttributeMaxDynamicSharedMemorySize, SMEM_CONV);
    cudaFuncSetAttribute(k_gram_mma, cudaFuncAttributeMaxDynamicSharedMemorySize, SMEM_DYN);

    k_init<<<1, 32>>>();
    k_splitw<<<(3 * Cdim * Cdim + 255) / 256, 256>>>(cw);
    k_split_in<<<(BN * Cdim / 4) / 256, 256>>>(x);

    dim3 gc(Cdim / 128, BN / 256);      // (6, 128)
    k_conv_mma<<<gc, 512, SMEM_CONV>>>(x);

    k_ln<<<BN, 256>>>(gma, bta, sw, sb);

    dim3 gg(136, 1, Bsz);               // upper-triangle tiles x batches
    k_gram_mma<<<gg, 256, SMEM_DYN>>>();

    dim3 gr(Ntok, Bsz);
    k_top3<<<gr, 256>>>(noise);
    k_dmin<<<gr, 256>>>();
    k_top2<<<Bsz, 256>>>();
    k_assign<<<BN / 256, 256>>>();
    k_norm<<<BN / 256, 256>>>(out, out_size);
    k_zero<<<(Bsz * 2 * Cdim + 127) / 128, 128>>>(out);
    dim3 gm(Cdim / 128, Bsz, Ntok / 256);   // (6, 16, 8)
    k_merge<<<gm, 128>>>(out);
}